// round 13
// baseline (speedup 1.0000x reference)
#include <cuda_runtime.h>
#include <cuda_fp16.h>

#define BB 4
#define SS 256
#define HH 128
#define NR 40
#define TI 8
#define NT 1024

// ---- shared layout (byte offsets) ----
// Phase A region (fp32):
#define AB_QW  0            // 20480  qw
#define AB_KW  20480        // 20480  kw
#define AB_REL 40960        // 20480  rel
#define AB_K   61440        // 4096   key tile (8 rows x 128 f32)  -> ends 65536
// Phase C overlay of the same region:
#define CB_VAL 0            // half[32768] value[b]  (65536 B)
#define CB_VW  65536        // half[5120]  vw        (10240 B)
#define B_E12  75776        // int2[2048]   (phase C: float4[1024] partials overlay)
#define B_P2   92160        // float2[2048]
#define SMEM_BYTES 108544

typedef unsigned long long ull;

__device__ __forceinline__ ull mul2(ull a, ull b) {
    ull d; asm("mul.rn.f32x2 %0, %1, %2;" : "=l"(d) : "l"(a), "l"(b)); return d;
}
__device__ __forceinline__ ull fma2(ull a, ull b, ull c) {
    ull d; asm("fma.rn.f32x2 %0, %1, %2, %3;" : "=l"(d) : "l"(a), "l"(b), "l"(c)); return d;
}
__device__ __forceinline__ ull add2(ull a, ull b) {
    ull d; asm("add.rn.f32x2 %0, %1, %2;" : "=l"(d) : "l"(a), "l"(b)); return d;
}
__device__ __forceinline__ void upk(ull v, float& lo, float& hi) {
    asm("mov.b64 {%0, %1}, %2;" : "=f"(lo), "=f"(hi) : "l"(v));
}
__device__ __forceinline__ ull pk(float lo, float hi) {
    ull r; asm("mov.b64 %0, {%1, %2};" : "=l"(r) : "f"(lo), "f"(hi)); return r;
}
__device__ __forceinline__ float tanhap(float x) {
    float r; asm("tanh.approx.f32 %0, %1;" : "=f"(r) : "f"(x)); return r;
}
__device__ __forceinline__ ull tanh2(ull x) {
    float lo, hi; upk(x, lo, hi);
    return pk(tanhap(lo), tanhap(hi));
}
__device__ __forceinline__ __half2 u2h(unsigned u) { __half2 h; *(unsigned*)&h = u; return h; }
__device__ __forceinline__ unsigned h2u(__half2 h) { return *(unsigned*)&h; }

__global__ void __launch_bounds__(NT, 1)
rgat_kernel(const float* __restrict__ query, const float* __restrict__ key,
            const float* __restrict__ value, const float* __restrict__ rel_emb,
            const float* __restrict__ qw_emb, const float* __restrict__ kw_emb,
            const float* __restrict__ vw_emb, const int* __restrict__ src_len,
            const int* __restrict__ rel_idx, float* __restrict__ out)
{
    extern __shared__ __align__(16) char smc[];
    int2*   sh_e12 = (int2*)(smc + B_E12);
    float2* sh_p2  = (float2*)(smc + B_P2);

    const int tid = threadIdx.x;
    const int b  = blockIdx.x / (SS / TI);
    const int i0 = (blockIdx.x % (SS / TI)) * TI;
    const int srclen = src_len[b];

    const int TBL = NR * HH; // 5120

    // ---- stage tables (fp32) ----
    {
        float* sh_qw  = (float*)(smc + AB_QW);
        float* sh_kw  = (float*)(smc + AB_KW);
        float* sh_rel = (float*)(smc + AB_REL);
        for (int k = tid * 4; k < TBL; k += NT * 4) {
            *(float4*)(sh_qw  + k) = *(const float4*)(qw_emb  + k);
            *(float4*)(sh_kw  + k) = *(const float4*)(kw_emb  + k);
            *(float4*)(sh_rel + k) = *(const float4*)(rel_emb + k);
        }
        // key tile: rows i0..i0+7
        float* sh_k = (float*)(smc + AB_K);
        const float* kb = key + ((size_t)b * SS + i0) * HH;
        for (int k = tid * 4; k < TI * HH; k += NT * 4)
            *(float4*)(sh_k + k) = *(const float4*)(kb + k);
    }

    // ---- stage e12: .x = e1 = rel_idx[b,j,i0+ii] (transpose), .y = e2 = rel_idx[b,i0+ii,j] ----
    if (tid < 512) {
        int j = tid >> 1;
        int c = (tid & 1) * 4;
        int4 v = *(const int4*)(rel_idx + ((size_t)b * SS + j) * SS + i0 + c);
        sh_e12[(c + 0) * SS + j].x = v.x;
        sh_e12[(c + 1) * SS + j].x = v.y;
        sh_e12[(c + 2) * SS + j].x = v.z;
        sh_e12[(c + 3) * SS + j].x = v.w;

        int ii = tid >> 6;
        int j4 = (tid & 63) * 4;
        int4 u = *(const int4*)(rel_idx + ((size_t)b * SS + i0 + ii) * SS + j4);
        sh_e12[ii * SS + j4 + 0].y = u.x;
        sh_e12[ii * SS + j4 + 1].y = u.y;
        sh_e12[ii * SS + j4 + 2].y = u.z;
        sh_e12[ii * SS + j4 + 3].y = u.w;
    }
    __syncthreads();

    const int w    = tid >> 5;
    const int lane = tid & 31;

    // ================= Phase A: scores (transposed nest) =================
    // warp owns 4 consecutive j (one per 8-lane group), q[j] in registers,
    // loops over the tile's 8 i rows. k tile loads broadcast across groups.
    {
        const int g   = lane >> 3;
        const int lig = lane & 7;
        const int jloc = (w << 2) + g;   // 0..127

        const float* sh_k   = (const float*)(smc + AB_K);
        const float* sh_qw  = (const float*)(smc + AB_QW);
        const float* sh_kw  = (const float*)(smc + AB_KW);
        const float* sh_rel = (const float*)(smc + AB_REL);

        #pragma unroll
        for (int batch = 0; batch < 2; batch++) {
            const int j = jloc + (batch << 7);
            if (batch && ((w << 2) + 128 >= srclen)) {   // warp-uniform: all 4 groups invalid
                if (lig == 0) {
                    #pragma unroll
                    for (int i = 0; i < TI; i++)
                        sh_p2[i * SS + j] = make_float2(-1e18f, 0.0f);
                }
                continue;
            }
            const bool jvalid = (j < srclen);            // group-uniform

            const float* qg = query + ((size_t)b * SS + j) * HH + lig * 16;
            const ulonglong2 q0 = *(const ulonglong2*)(qg + 0);
            const ulonglong2 q1 = *(const ulonglong2*)(qg + 4);
            const ulonglong2 q2 = *(const ulonglong2*)(qg + 8);
            const ulonglong2 q3 = *(const ulonglong2*)(qg + 12);

            for (int i = 0; i < TI; i++) {
                const int2 e = sh_e12[i * SS + j];
                const float* kp  = sh_k   + i   * HH + lig * 16;
                const float* qwp = sh_qw  + e.x * HH + lig * 16;
                const float* kwp = sh_kw  + e.y * HH + lig * 16;
                const float* rp  = sh_rel + e.x * HH + lig * 16;

                ull a0 = 0, a1 = 0, a2 = 0, a3 = 0;
#define ASTEP(QQ, OFF, ACC) { \
                const ulonglong2 kk = *(const ulonglong2*)(kp  + OFF); \
                const ulonglong2 qw = *(const ulonglong2*)(qwp + OFF); \
                const ulonglong2 kw = *(const ulonglong2*)(kwp + OFF); \
                const ulonglong2 r  = *(const ulonglong2*)(rp  + OFF); \
                ACC = fma2(r.x, tanh2(fma2(qw.x, QQ.x, mul2(kw.x, kk.x))), ACC); \
                ACC = fma2(r.y, tanh2(fma2(qw.y, QQ.y, mul2(kw.y, kk.y))), ACC); }
                ASTEP(q0,  0, a0)
                ASTEP(q1,  4, a1)
                ASTEP(q2,  8, a2)
                ASTEP(q3, 12, a3)
#undef ASTEP
                ull s2 = add2(add2(a0, a1), add2(a2, a3));
                float slo, shi; upk(s2, slo, shi);
                float acc = slo + shi;
                // 8-lane group butterfly (xor offsets stay within the group)
                acc += __shfl_xor_sync(0xffffffffu, acc, 4);
                acc += __shfl_xor_sync(0xffffffffu, acc, 2);
                acc += __shfl_xor_sync(0xffffffffu, acc, 1);
                if (lig == 0) {
                    float sv = jvalid ? acc : -1e18f;
                    sh_p2[i * SS + j] = make_float2(sv, __int_as_float(e.x));
                }
            }
        }
    }
    __syncthreads();

    // ---- restage value[b] and vw as fp16 over the phase-A region ----
    #define CVT8(DSTOFF, SRC, K) { \
        float4 a = *(const float4*)((SRC) + (K)); \
        float4 c = *(const float4*)((SRC) + (K) + 4); \
        uint4 u; \
        u.x = h2u(__floats2half2_rn(a.x, a.y)); \
        u.y = h2u(__floats2half2_rn(a.z, a.w)); \
        u.z = h2u(__floats2half2_rn(c.x, c.y)); \
        u.w = h2u(__floats2half2_rn(c.z, c.w)); \
        *(uint4*)(smc + (DSTOFF) + (K) * 2) = u; }

    const float* vb = value + (size_t)b * SS * HH;
    for (int k = tid * 8; k < SS * HH; k += NT * 8)
        CVT8(CB_VAL, vb, k)
    for (int k = tid * 8; k < NR * HH; k += NT * 8)
        CVT8(CB_VW, vw_emb, k)
    #undef CVT8

    // ================= Phase B: softmax, pre-normalized (warps 0..7) =========
    if (w < TI) {
        float2 vals[8];
        float m = -3.0e38f;
        #pragma unroll
        for (int k = 0; k < 8; k++) {
            vals[k] = sh_p2[w * SS + lane + k * 32];
            m = fmaxf(m, vals[k].x);
        }
        #pragma unroll
        for (int o = 16; o; o >>= 1) m = fmaxf(m, __shfl_xor_sync(0xffffffffu, m, o));
        float ssum = 0.0f;
        #pragma unroll
        for (int k = 0; k < 8; k++) {
            float e = __expf(vals[k].x - m);   // masked -> 0
            vals[k].x = e;
            ssum += e;
        }
        #pragma unroll
        for (int o = 16; o; o >>= 1) ssum += __shfl_xor_sync(0xffffffffu, ssum, o);
        const float inv = 1.0f / ssum;
        #pragma unroll
        for (int k = 0; k < 8; k++)
            sh_p2[w * SS + lane + k * 32] = make_float2(vals[k].x * inv, vals[k].y);
    }
    __syncthreads();

    // ================= Phase C: output (fp16 operands, fp32 accumulate) =====
    float4* part4 = (float4*)(smc + B_E12);   // overlay (e12 dead), 1024 x float4
    {
        const int ci = tid >> 7;              // 0..7
        const int sub = tid & 127;
        const int jp = sub >> 5;              // 0..3 (warp-uniform)
        const int hq = sub & 31;              // h-quad, h = hq*4
        const float2* prow = sh_p2 + ci * SS;
        const char* vwb = smc + CB_VW  + hq * 8;
        const char* vvb = smc + CB_VAL + hq * 8;
        float4 acc = make_float4(0.0f, 0.0f, 0.0f, 0.0f);
        #pragma unroll 4
        for (int j = jp; j < srclen; j += 4) {
            const float2 pe = prow[j];
            const int e1 = __float_as_int(pe.y);
            const uint2 wu = *(const uint2*)(vwb + e1 * 256);
            const uint2 vu = *(const uint2*)(vvb + j  * 256);
            const float2 f0 = __half22float2(__hmul2(u2h(wu.x), u2h(vu.x)));
            const float2 f1 = __half22float2(__hmul2(u2h(wu.y), u2h(vu.y)));
            acc.x = fmaf(pe.x, f0.x, acc.x);
            acc.y = fmaf(pe.x, f0.y, acc.y);
            acc.z = fmaf(pe.x, f1.x, acc.z);
            acc.w = fmaf(pe.x, f1.y, acc.w);
        }
        part4[tid] = acc;
    }
    __syncthreads();
    if (tid < 256) {
        const int ci = tid >> 5;              // 0..7
        const int hq = tid & 31;
        const float4 r0 = part4[ci * 128 +  0 + hq];
        const float4 r1 = part4[ci * 128 + 32 + hq];
        const float4 r2 = part4[ci * 128 + 64 + hq];
        const float4 r3 = part4[ci * 128 + 96 + hq];
        float4 o;
        o.x = (r0.x + r1.x) + (r2.x + r3.x);
        o.y = (r0.y + r1.y) + (r2.y + r3.y);
        o.z = (r0.z + r1.z) + (r2.z + r3.z);
        o.w = (r0.w + r1.w) + (r2.w + r3.w);
        *(float4*)(out + ((size_t)b * SS + i0 + ci) * HH + hq * 4) = o;
    }
}

extern "C" void kernel_launch(void* const* d_in, const int* in_sizes, int n_in,
                              void* d_out, int out_size) {
    const float* query   = (const float*)d_in[0];
    const float* key_t   = (const float*)d_in[1];
    const float* value   = (const float*)d_in[2];
    const float* rel_emb = (const float*)d_in[3];
    const float* qw_emb  = (const float*)d_in[4];
    const float* kw_emb  = (const float*)d_in[5];
    const float* vw_emb  = (const float*)d_in[6];
    const int*   src_len = (const int*)d_in[7];
    const int*   rel_idx = (const int*)d_in[8];
    float* out = (float*)d_out;

    cudaFuncSetAttribute(rgat_kernel,
                         cudaFuncAttributeMaxDynamicSharedMemorySize, SMEM_BYTES);

    rgat_kernel<<<BB * (SS / TI), NT, SMEM_BYTES>>>(
        query, key_t, value, rel_emb, qw_emb, kw_emb, vw_emb,
        src_len, rel_idx, out);
}

// round 14
// speedup vs baseline: 2.4625x; 2.4625x over previous
#include <cuda_runtime.h>
#include <cuda_fp16.h>

#define BB 4
#define SS 256
#define HH 128
#define NR 40
#define TI 8
#define NT 1024

// ---- shared layout (byte offsets) ----
// Phase A region (fp32):
#define AB_QW  0            // 20480  qw
#define AB_KW  20480        // 20480  kw
#define AB_REL 40960        // 20480  rel
#define AB_K   61440        // 4096   key tile (8 rows x 128 f32)  -> ends 65536
// Phase C overlay of the same region:
#define CB_VAL 0            // half[32768] value[b]  (65536 B)
#define CB_VW  65536        // half[5120]  vw        (10240 B)
#define B_E12  75776        // int2[2048]   (phase C: float4[1024] partials overlay)
#define B_P2   92160        // float2[2048]
#define SMEM_BYTES 108544

typedef unsigned long long ull;

__device__ __forceinline__ ull mul2(ull a, ull b) {
    ull d; asm("mul.rn.f32x2 %0, %1, %2;" : "=l"(d) : "l"(a), "l"(b)); return d;
}
__device__ __forceinline__ ull fma2(ull a, ull b, ull c) {
    ull d; asm("fma.rn.f32x2 %0, %1, %2, %3;" : "=l"(d) : "l"(a), "l"(b), "l"(c)); return d;
}
__device__ __forceinline__ ull add2(ull a, ull b) {
    ull d; asm("add.rn.f32x2 %0, %1, %2;" : "=l"(d) : "l"(a), "l"(b)); return d;
}
__device__ __forceinline__ void upk(ull v, float& lo, float& hi) {
    asm("mov.b64 {%0, %1}, %2;" : "=f"(lo), "=f"(hi) : "l"(v));
}
__device__ __forceinline__ ull pk(float lo, float hi) {
    ull r; asm("mov.b64 %0, {%1, %2};" : "=l"(r) : "f"(lo), "f"(hi)); return r;
}
__device__ __forceinline__ float tanhap(float x) {
    float r; asm("tanh.approx.f32 %0, %1;" : "=f"(r) : "f"(x)); return r;
}
__device__ __forceinline__ ull tanh2(ull x) {
    float lo, hi; upk(x, lo, hi);
    return pk(tanhap(lo), tanhap(hi));
}
__device__ __forceinline__ __half2 u2h(unsigned u) { __half2 h; *(unsigned*)&h = u; return h; }
__device__ __forceinline__ unsigned h2u(__half2 h) { return *(unsigned*)&h; }

__global__ void __launch_bounds__(NT, 1)
rgat_kernel(const float* __restrict__ query, const float* __restrict__ key,
            const float* __restrict__ value, const float* __restrict__ rel_emb,
            const float* __restrict__ qw_emb, const float* __restrict__ kw_emb,
            const float* __restrict__ vw_emb, const int* __restrict__ src_len,
            const int* __restrict__ rel_idx, float* __restrict__ out)
{
    extern __shared__ __align__(16) char smc[];
    int2*   sh_e12 = (int2*)(smc + B_E12);
    float2* sh_p2  = (float2*)(smc + B_P2);

    const int tid = threadIdx.x;
    const int b  = blockIdx.x / (SS / TI);
    const int i0 = (blockIdx.x % (SS / TI)) * TI;
    const int srclen = src_len[b];

    const int TBL = NR * HH; // 5120

    // ---- stage tables (fp32) + key tile ----
    {
        float* sh_qw  = (float*)(smc + AB_QW);
        float* sh_kw  = (float*)(smc + AB_KW);
        float* sh_rel = (float*)(smc + AB_REL);
        for (int k = tid * 4; k < TBL; k += NT * 4) {
            *(float4*)(sh_qw  + k) = *(const float4*)(qw_emb  + k);
            *(float4*)(sh_kw  + k) = *(const float4*)(kw_emb  + k);
            *(float4*)(sh_rel + k) = *(const float4*)(rel_emb + k);
        }
        float* sh_k = (float*)(smc + AB_K);
        const float* kb = key + ((size_t)b * SS + i0) * HH;
        for (int k = tid * 4; k < TI * HH; k += NT * 4)
            *(float4*)(sh_k + k) = *(const float4*)(kb + k);
    }

    // ---- stage e12: .x = e1 = rel_idx[b,j,i0+ii] (transpose), .y = e2 = rel_idx[b,i0+ii,j] ----
    if (tid < 512) {
        int j = tid >> 1;
        int c = (tid & 1) * 4;
        int4 v = *(const int4*)(rel_idx + ((size_t)b * SS + j) * SS + i0 + c);
        sh_e12[(c + 0) * SS + j].x = v.x;
        sh_e12[(c + 1) * SS + j].x = v.y;
        sh_e12[(c + 2) * SS + j].x = v.z;
        sh_e12[(c + 3) * SS + j].x = v.w;

        int ii = tid >> 6;
        int j4 = (tid & 63) * 4;
        int4 u = *(const int4*)(rel_idx + ((size_t)b * SS + i0 + ii) * SS + j4);
        sh_e12[ii * SS + j4 + 0].y = u.x;
        sh_e12[ii * SS + j4 + 1].y = u.y;
        sh_e12[ii * SS + j4 + 2].y = u.z;
        sh_e12[ii * SS + j4 + 3].y = u.w;
    }
    __syncthreads();

    const int w    = tid >> 5;
    const int lane = tid & 31;

    // ================= Phase A: scores (transposed nest, R12 addressing) ======
    // warp owns 4 consecutive j (one per 8-lane group); q[j] in registers
    // (coalesced gmem read, interleaved chunks OFF = 0/32/64/96 + lig*4);
    // loops over the tile's 8 i rows with k broadcast from smem.
    {
        const int g   = lane >> 3;
        const int lig = lane & 7;
        const int jloc = (w << 2) + g;   // 0..127

        const float* sh_k   = (const float*)(smc + AB_K);
        const float* sh_qw  = (const float*)(smc + AB_QW);
        const float* sh_kw  = (const float*)(smc + AB_KW);
        const float* sh_rel = (const float*)(smc + AB_REL);

        #pragma unroll
        for (int batch = 0; batch < 2; batch++) {
            const int j = jloc + (batch << 7);
            if (batch && ((w << 2) + 128 >= srclen)) {   // warp-uniform: all 4 groups invalid
                if (lig == 0) {
                    #pragma unroll
                    for (int i = 0; i < TI; i++)
                        sh_p2[i * SS + j] = make_float2(-1e18f, 0.0f);
                }
                continue;
            }
            const bool jvalid = !batch || (j < srclen);   // group-uniform

            // q[j] into regs: same interleaved chunks as smem operands
            const float* qg = query + ((size_t)b * SS + j) * HH + lig * 4;
            const ulonglong2 q0 = *(const ulonglong2*)(qg + 0);
            const ulonglong2 q1 = *(const ulonglong2*)(qg + 32);
            const ulonglong2 q2 = *(const ulonglong2*)(qg + 64);
            const ulonglong2 q3 = *(const ulonglong2*)(qg + 96);

            #pragma unroll 2
            for (int i = 0; i < TI; i++) {
                const int2 e = sh_e12[i * SS + j];
                const float* kp  = sh_k   + i   * HH + lig * 4;
                const float* qwp = sh_qw  + e.x * HH + lig * 4;
                const float* kwp = sh_kw  + e.y * HH + lig * 4;
                const float* rp  = sh_rel + e.x * HH + lig * 4;

                ull a0 = 0, a1 = 0, a2 = 0, a3 = 0;
#define ASTEP(QQ, OFF, ACC) { \
                const ulonglong2 kk = *(const ulonglong2*)(kp  + OFF); \
                const ulonglong2 qw = *(const ulonglong2*)(qwp + OFF); \
                const ulonglong2 kw = *(const ulonglong2*)(kwp + OFF); \
                const ulonglong2 r  = *(const ulonglong2*)(rp  + OFF); \
                ACC = fma2(r.x, tanh2(fma2(qw.x, QQ.x, mul2(kw.x, kk.x))), ACC); \
                ACC = fma2(r.y, tanh2(fma2(qw.y, QQ.y, mul2(kw.y, kk.y))), ACC); }
                ASTEP(q0,  0, a0)
                ASTEP(q1, 32, a1)
                ASTEP(q2, 64, a2)
                ASTEP(q3, 96, a3)
#undef ASTEP
                ull s2 = add2(add2(a0, a1), add2(a2, a3));
                float slo, shi; upk(s2, slo, shi);
                float acc = slo + shi;
                // 8-lane group butterfly (xor offsets stay within the group)
                acc += __shfl_xor_sync(0xffffffffu, acc, 4);
                acc += __shfl_xor_sync(0xffffffffu, acc, 2);
                acc += __shfl_xor_sync(0xffffffffu, acc, 1);
                if (lig == 0) {
                    float sv = jvalid ? acc : -1e18f;
                    sh_p2[i * SS + j] = make_float2(sv, __int_as_float(e.x));
                }
            }
        }
    }
    __syncthreads();

    // ---- restage value[b] and vw as fp16 over the phase-A region ----
    #define CVT8(DSTOFF, SRC, K) { \
        float4 a = *(const float4*)((SRC) + (K)); \
        float4 c = *(const float4*)((SRC) + (K) + 4); \
        uint4 u; \
        u.x = h2u(__floats2half2_rn(a.x, a.y)); \
        u.y = h2u(__floats2half2_rn(a.z, a.w)); \
        u.z = h2u(__floats2half2_rn(c.x, c.y)); \
        u.w = h2u(__floats2half2_rn(c.z, c.w)); \
        *(uint4*)(smc + (DSTOFF) + (K) * 2) = u; }

    const float* vb = value + (size_t)b * SS * HH;
    for (int k = tid * 8; k < SS * HH; k += NT * 8)
        CVT8(CB_VAL, vb, k)
    for (int k = tid * 8; k < NR * HH; k += NT * 8)
        CVT8(CB_VW, vw_emb, k)
    #undef CVT8

    // ================= Phase B: softmax, pre-normalized (warps 0..7) =========
    if (w < TI) {
        float2 vals[8];
        float m = -3.0e38f;
        #pragma unroll
        for (int k = 0; k < 8; k++) {
            vals[k] = sh_p2[w * SS + lane + k * 32];
            m = fmaxf(m, vals[k].x);
        }
        #pragma unroll
        for (int o = 16; o; o >>= 1) m = fmaxf(m, __shfl_xor_sync(0xffffffffu, m, o));
        float ssum = 0.0f;
        #pragma unroll
        for (int k = 0; k < 8; k++) {
            float e = __expf(vals[k].x - m);   // masked -> 0
            vals[k].x = e;
            ssum += e;
        }
        #pragma unroll
        for (int o = 16; o; o >>= 1) ssum += __shfl_xor_sync(0xffffffffu, ssum, o);
        const float inv = 1.0f / ssum;
        #pragma unroll
        for (int k = 0; k < 8; k++)
            sh_p2[w * SS + lane + k * 32] = make_float2(vals[k].x * inv, vals[k].y);
    }
    __syncthreads();

    // ================= Phase C: output (fp16 operands, fp32 accumulate) =====
    float4* part4 = (float4*)(smc + B_E12);   // overlay (e12 dead), 1024 x float4
    {
        const int ci = tid >> 7;              // 0..7
        const int sub = tid & 127;
        const int jp = sub >> 5;              // 0..3 (warp-uniform)
        const int hq = sub & 31;              // h-quad, h = hq*4
        const float2* prow = sh_p2 + ci * SS;
        const char* vwb = smc + CB_VW  + hq * 8;
        const char* vvb = smc + CB_VAL + hq * 8;
        float4 acc = make_float4(0.0f, 0.0f, 0.0f, 0.0f);
        #pragma unroll 4
        for (int j = jp; j < srclen; j += 4) {
            const float2 pe = prow[j];
            const int e1 = __float_as_int(pe.y);
            const uint2 wu = *(const uint2*)(vwb + e1 * 256);
            const uint2 vu = *(const uint2*)(vvb + j  * 256);
            const float2 f0 = __half22float2(__hmul2(u2h(wu.x), u2h(vu.x)));
            const float2 f1 = __half22float2(__hmul2(u2h(wu.y), u2h(vu.y)));
            acc.x = fmaf(pe.x, f0.x, acc.x);
            acc.y = fmaf(pe.x, f0.y, acc.y);
            acc.z = fmaf(pe.x, f1.x, acc.z);
            acc.w = fmaf(pe.x, f1.y, acc.w);
        }
        part4[tid] = acc;
    }
    __syncthreads();
    if (tid < 256) {
        const int ci = tid >> 5;              // 0..7
        const int hq = tid & 31;
        const float4 r0 = part4[ci * 128 +  0 + hq];
        const float4 r1 = part4[ci * 128 + 32 + hq];
        const float4 r2 = part4[ci * 128 + 64 + hq];
        const float4 r3 = part4[ci * 128 + 96 + hq];
        float4 o;
        o.x = (r0.x + r1.x) + (r2.x + r3.x);
        o.y = (r0.y + r1.y) + (r2.y + r3.y);
        o.z = (r0.z + r1.z) + (r2.z + r3.z);
        o.w = (r0.w + r1.w) + (r2.w + r3.w);
        *(float4*)(out + ((size_t)b * SS + i0 + ci) * HH + hq * 4) = o;
    }
}

extern "C" void kernel_launch(void* const* d_in, const int* in_sizes, int n_in,
                              void* d_out, int out_size) {
    const float* query   = (const float*)d_in[0];
    const float* key_t   = (const float*)d_in[1];
    const float* value   = (const float*)d_in[2];
    const float* rel_emb = (const float*)d_in[3];
    const float* qw_emb  = (const float*)d_in[4];
    const float* kw_emb  = (const float*)d_in[5];
    const float* vw_emb  = (const float*)d_in[6];
    const int*   src_len = (const int*)d_in[7];
    const int*   rel_idx = (const int*)d_in[8];
    float* out = (float*)d_out;

    cudaFuncSetAttribute(rgat_kernel,
                         cudaFuncAttributeMaxDynamicSharedMemorySize, SMEM_BYTES);

    rgat_kernel<<<BB * (SS / TI), NT, SMEM_BYTES>>>(
        query, key_t, value, rel_emb, qw_emb, kw_emb, vw_emb,
        src_len, rel_idx, out);
}

// round 15
// speedup vs baseline: 2.4761x; 1.0055x over previous
#include <cuda_runtime.h>
#include <cuda_fp16.h>

#define BB 4
#define SS 256
#define HH 128
#define NR 40
#define TI 8
#define NT 1024

// ---- shared layout (byte offsets, non-overlapping) ----
#define AB_QW   0            // 20480  qw  fp32
#define AB_KW   20480        // 20480  kw  fp32
#define AB_K    40960        // 4096   key tile fp32 (8 x 128)
#define AB_RELH 45056        // 10240  rel fp16
#define CB_VAL  55296        // 65536  value[b] fp16
#define CB_VW   120832       // 10240  vw fp16
#define B_E12   131072       // int2[2048] (phase C: float4[1024] partials overlay)
#define B_P2    147456       // float2[2048]
#define SMEM_BYTES 163840

typedef unsigned long long ull;

__device__ __forceinline__ ull mul2(ull a, ull b) {
    ull d; asm("mul.rn.f32x2 %0, %1, %2;" : "=l"(d) : "l"(a), "l"(b)); return d;
}
__device__ __forceinline__ ull fma2(ull a, ull b, ull c) {
    ull d; asm("fma.rn.f32x2 %0, %1, %2, %3;" : "=l"(d) : "l"(a), "l"(b), "l"(c)); return d;
}
__device__ __forceinline__ ull add2(ull a, ull b) {
    ull d; asm("add.rn.f32x2 %0, %1, %2;" : "=l"(d) : "l"(a), "l"(b)); return d;
}
__device__ __forceinline__ void upk(ull v, float& lo, float& hi) {
    asm("mov.b64 {%0, %1}, %2;" : "=f"(lo), "=f"(hi) : "l"(v));
}
__device__ __forceinline__ ull pk(float lo, float hi) {
    ull r; asm("mov.b64 %0, {%1, %2};" : "=l"(r) : "f"(lo), "f"(hi)); return r;
}
__device__ __forceinline__ float tanhap(float x) {
    float r; asm("tanh.approx.f32 %0, %1;" : "=f"(r) : "f"(x)); return r;
}
__device__ __forceinline__ ull tanh2(ull x) {
    float lo, hi; upk(x, lo, hi);
    return pk(tanhap(lo), tanhap(hi));
}
__device__ __forceinline__ __half2 u2h(unsigned u) { __half2 h; *(unsigned*)&h = u; return h; }
__device__ __forceinline__ unsigned h2u(__half2 h) { return *(unsigned*)&h; }
__device__ __forceinline__ ull h2f2(unsigned u) {     // half2 -> packed f32x2
    float2 f = __half22float2(u2h(u));
    return pk(f.x, f.y);
}
__device__ __forceinline__ void cp16(unsigned smem_dst, const void* gsrc) {
    asm volatile("cp.async.cg.shared.global [%0], [%1], 16;"
                 :: "r"(smem_dst), "l"(gsrc) : "memory");
}

__global__ void __launch_bounds__(NT, 1)
rgat_kernel(const float* __restrict__ query, const float* __restrict__ key,
            const float* __restrict__ value, const float* __restrict__ rel_emb,
            const float* __restrict__ qw_emb, const float* __restrict__ kw_emb,
            const float* __restrict__ vw_emb, const int* __restrict__ src_len,
            const int* __restrict__ rel_idx, float* __restrict__ out)
{
    extern __shared__ __align__(16) char smc[];
    int2*   sh_e12 = (int2*)(smc + B_E12);
    float2* sh_p2  = (float2*)(smc + B_P2);

    const int tid = threadIdx.x;
    const int b  = blockIdx.x / (SS / TI);
    const int i0 = (blockIdx.x % (SS / TI)) * TI;
    const int srclen = src_len[b];

    const int TBL = NR * HH; // 5120
    const unsigned smb = (unsigned)__cvta_generic_to_shared(smc);

    // ---- cp.async staging: qw, kw (fp32 tables), key tile ----
    for (int k = tid * 4; k < TBL; k += NT * 4) {
        cp16(smb + AB_QW + k * 4, qw_emb + k);
        cp16(smb + AB_KW + k * 4, kw_emb + k);
    }
    {
        const float* kb = key + ((size_t)b * SS + i0) * HH;
        if (tid < 256) cp16(smb + AB_K + tid * 16, kb + tid * 4);
    }
    asm volatile("cp.async.commit_group;" ::: "memory");

    // ---- rel -> fp16 ----
    for (int k = tid * 4; k < TBL; k += NT * 4) {
        float4 r = *(const float4*)(rel_emb + k);
        uint2 u;
        u.x = h2u(__floats2half2_rn(r.x, r.y));
        u.y = h2u(__floats2half2_rn(r.z, r.w));
        *(uint2*)(smc + AB_RELH + k * 2) = u;
    }

    // ---- value[b], vw -> fp16 (upfront; no mid-kernel restage) ----
    #define CVT8(DSTOFF, SRC, K) { \
        float4 a = *(const float4*)((SRC) + (K)); \
        float4 c = *(const float4*)((SRC) + (K) + 4); \
        uint4 u; \
        u.x = h2u(__floats2half2_rn(a.x, a.y)); \
        u.y = h2u(__floats2half2_rn(a.z, a.w)); \
        u.z = h2u(__floats2half2_rn(c.x, c.y)); \
        u.w = h2u(__floats2half2_rn(c.z, c.w)); \
        *(uint4*)(smc + (DSTOFF) + (K) * 2) = u; }

    const float* vb = value + (size_t)b * SS * HH;
    for (int k = tid * 8; k < SS * HH; k += NT * 8)
        CVT8(CB_VAL, vb, k)
    for (int k = tid * 8; k < TBL; k += NT * 8)
        CVT8(CB_VW, vw_emb, k)
    #undef CVT8

    // ---- stage e12: .x = e1 = rel_idx[b,j,i0+ii] (transpose), .y = e2 = rel_idx[b,i0+ii,j] ----
    if (tid < 512) {
        int j = tid >> 1;
        int c = (tid & 1) * 4;
        int4 v = *(const int4*)(rel_idx + ((size_t)b * SS + j) * SS + i0 + c);
        sh_e12[(c + 0) * SS + j].x = v.x;
        sh_e12[(c + 1) * SS + j].x = v.y;
        sh_e12[(c + 2) * SS + j].x = v.z;
        sh_e12[(c + 3) * SS + j].x = v.w;

        int ii = tid >> 6;
        int j4 = (tid & 63) * 4;
        int4 u = *(const int4*)(rel_idx + ((size_t)b * SS + i0 + ii) * SS + j4);
        sh_e12[ii * SS + j4 + 0].y = u.x;
        sh_e12[ii * SS + j4 + 1].y = u.y;
        sh_e12[ii * SS + j4 + 2].y = u.z;
        sh_e12[ii * SS + j4 + 3].y = u.w;
    }
    asm volatile("cp.async.wait_group 0;" ::: "memory");
    __syncthreads();

    const int w    = tid >> 5;
    const int lane = tid & 31;

    // ================= Phase A: scores =================
    // warp owns 4 consecutive j (one per 8-lane group); q[j] in registers;
    // loops over the tile's 8 i rows with k broadcast from smem.
    // qw/kw fp32 (tanh-arg path), rel fp16 (output-mult path).
    {
        const int g   = lane >> 3;
        const int lig = lane & 7;
        const int jloc = (w << 2) + g;   // 0..127

        const float* sh_k  = (const float*)(smc + AB_K);
        const float* sh_qw = (const float*)(smc + AB_QW);
        const float* sh_kw = (const float*)(smc + AB_KW);

        #pragma unroll
        for (int batch = 0; batch < 2; batch++) {
            const int j = jloc + (batch << 7);
            if (batch && ((w << 2) + 128 >= srclen)) {   // warp-uniform early-out
                if (lig == 0) {
                    #pragma unroll
                    for (int i = 0; i < TI; i++)
                        sh_p2[i * SS + j] = make_float2(-1e18f, 0.0f);
                }
                continue;
            }
            const bool jvalid = !batch || (j < srclen);   // group-uniform

            const float* qg = query + ((size_t)b * SS + j) * HH + lig * 4;
            const ulonglong2 q0 = *(const ulonglong2*)(qg + 0);
            const ulonglong2 q1 = *(const ulonglong2*)(qg + 32);
            const ulonglong2 q2 = *(const ulonglong2*)(qg + 64);
            const ulonglong2 q3 = *(const ulonglong2*)(qg + 96);

            #pragma unroll 2
            for (int i = 0; i < TI; i++) {
                const int2 e = sh_e12[i * SS + j];
                const float* kp  = sh_k  + i   * HH + lig * 4;
                const float* qwp = sh_qw + e.x * HH + lig * 4;
                const float* kwp = sh_kw + e.y * HH + lig * 4;
                const char*  rp  = smc + AB_RELH + e.x * 256 + lig * 8;

                ull a0 = 0, a1 = 0, a2 = 0, a3 = 0;
#define ASTEP(QQ, OFF, ACC) { \
                const ulonglong2 kk = *(const ulonglong2*)(kp  + OFF); \
                const ulonglong2 qw = *(const ulonglong2*)(qwp + OFF); \
                const ulonglong2 kw = *(const ulonglong2*)(kwp + OFF); \
                const uint2 ru = *(const uint2*)(rp + (OFF) * 2); \
                ACC = fma2(h2f2(ru.x), tanh2(fma2(qw.x, QQ.x, mul2(kw.x, kk.x))), ACC); \
                ACC = fma2(h2f2(ru.y), tanh2(fma2(qw.y, QQ.y, mul2(kw.y, kk.y))), ACC); }
                ASTEP(q0,  0, a0)
                ASTEP(q1, 32, a1)
                ASTEP(q2, 64, a2)
                ASTEP(q3, 96, a3)
#undef ASTEP
                ull s2 = add2(add2(a0, a1), add2(a2, a3));
                float slo, shi; upk(s2, slo, shi);
                float acc = slo + shi;
                // 8-lane group butterfly (xor offsets stay within the group)
                acc += __shfl_xor_sync(0xffffffffu, acc, 4);
                acc += __shfl_xor_sync(0xffffffffu, acc, 2);
                acc += __shfl_xor_sync(0xffffffffu, acc, 1);
                if (lig == 0) {
                    float sv = jvalid ? acc : -1e18f;
                    sh_p2[i * SS + j] = make_float2(sv, __int_as_float(e.x));
                }
            }
        }
    }
    __syncthreads();

    // ================= Phase B: softmax, pre-normalized (warps 0..7) =========
    if (w < TI) {
        float2 vals[8];
        float m = -3.0e38f;
        #pragma unroll
        for (int k = 0; k < 8; k++) {
            vals[k] = sh_p2[w * SS + lane + k * 32];
            m = fmaxf(m, vals[k].x);
        }
        #pragma unroll
        for (int o = 16; o; o >>= 1) m = fmaxf(m, __shfl_xor_sync(0xffffffffu, m, o));
        float ssum = 0.0f;
        #pragma unroll
        for (int k = 0; k < 8; k++) {
            float e = __expf(vals[k].x - m);   // masked -> 0
            vals[k].x = e;
            ssum += e;
        }
        #pragma unroll
        for (int o = 16; o; o >>= 1) ssum += __shfl_xor_sync(0xffffffffu, ssum, o);
        const float inv = 1.0f / ssum;
        #pragma unroll
        for (int k = 0; k < 8; k++)
            sh_p2[w * SS + lane + k * 32] = make_float2(vals[k].x * inv, vals[k].y);
    }
    __syncthreads();

    // ================= Phase C: output (fp16 operands, fp32 accumulate) =====
    float4* part4 = (float4*)(smc + B_E12);   // overlay (e12 dead), 1024 x float4
    {
        const int ci = tid >> 7;              // 0..7
        const int sub = tid & 127;
        const int jp = sub >> 5;              // 0..3 (warp-uniform)
        const int hq = sub & 31;              // h-quad, h = hq*4
        const float2* prow = sh_p2 + ci * SS;
        const char* vwb = smc + CB_VW  + hq * 8;
        const char* vvb = smc + CB_VAL + hq * 8;
        float4 acc = make_float4(0.0f, 0.0f, 0.0f, 0.0f);
        #pragma unroll 4
        for (int j = jp; j < srclen; j += 4) {
            const float2 pe = prow[j];
            const int e1 = __float_as_int(pe.y);
            const uint2 wu = *(const uint2*)(vwb + e1 * 256);
            const uint2 vu = *(const uint2*)(vvb + j  * 256);
            const float2 f0 = __half22float2(__hmul2(u2h(wu.x), u2h(vu.x)));
            const float2 f1 = __half22float2(__hmul2(u2h(wu.y), u2h(vu.y)));
            acc.x = fmaf(pe.x, f0.x, acc.x);
            acc.y = fmaf(pe.x, f0.y, acc.y);
            acc.z = fmaf(pe.x, f1.x, acc.z);
            acc.w = fmaf(pe.x, f1.y, acc.w);
        }
        part4[tid] = acc;
    }
    __syncthreads();
    if (tid < 256) {
        const int ci = tid >> 5;              // 0..7
        const int hq = tid & 31;
        const float4 r0 = part4[ci * 128 +  0 + hq];
        const float4 r1 = part4[ci * 128 + 32 + hq];
        const float4 r2 = part4[ci * 128 + 64 + hq];
        const float4 r3 = part4[ci * 128 + 96 + hq];
        float4 o;
        o.x = (r0.x + r1.x) + (r2.x + r3.x);
        o.y = (r0.y + r1.y) + (r2.y + r3.y);
        o.z = (r0.z + r1.z) + (r2.z + r3.z);
        o.w = (r0.w + r1.w) + (r2.w + r3.w);
        *(float4*)(out + ((size_t)b * SS + i0 + ci) * HH + hq * 4) = o;
    }
}

extern "C" void kernel_launch(void* const* d_in, const int* in_sizes, int n_in,
                              void* d_out, int out_size) {
    const float* query   = (const float*)d_in[0];
    const float* key_t   = (const float*)d_in[1];
    const float* value   = (const float*)d_in[2];
    const float* rel_emb = (const float*)d_in[3];
    const float* qw_emb  = (const float*)d_in[4];
    const float* kw_emb  = (const float*)d_in[5];
    const float* vw_emb  = (const float*)d_in[6];
    const int*   src_len = (const int*)d_in[7];
    const int*   rel_idx = (const int*)d_in[8];
    float* out = (float*)d_out;

    cudaFuncSetAttribute(rgat_kernel,
                         cudaFuncAttributeMaxDynamicSharedMemorySize, SMEM_BYTES);

    rgat_kernel<<<BB * (SS / TI), NT, SMEM_BYTES>>>(
        query, key_t, value, rel_emb, qw_emb, kw_emb, vw_emb,
        src_len, rel_idx, out);
}